// round 7
// baseline (speedup 1.0000x reference)
#include <cuda_runtime.h>
#include <math.h>

#define Nn 8
#define Tt 64
#define Aa 65536
#define Cc 80
#define NFLT4 (Aa * (Cc / 4))          // float4s of y_pred per image = 1,310,720
#define ITER 8
#define SBX_PER_N 640                   // stream blocks per image
#define SBX (SBX_PER_N * Nn)            // 5120
#define K1B ((Aa / 256) * Nn)           // 2048
#define TOTB (SBX + K1B)                // 7168
#define QB 64                           // correction blocks

#define F_EPS 1e-6f
#define SL1_BETA (1.0f / 9.0f)
#define LN2 0.69314718055994531f

// ---------------- scratch (device globals; no allocation) ----------------
__device__ unsigned char  g_state[Nn * Aa];  // 0=ignore 1=neg 2=pos
__device__ int            g_asg[Nn * Aa];    // bit30 = override, low bits = gt index t
__device__ int            g_nvalid[Nn];
__device__ unsigned char  g_vt[Nn * Tt];
__device__ unsigned char  g_label[Nn * Tt];
__device__ unsigned long long g_gtkey[Nn * Tt];
__device__ int            g_poscnt[Nn];
__device__ float          g_pcls[SBX];
__device__ float          g_qcls[QB];
__device__ float          g_qbox[QB];
__device__ unsigned       g_done1;
__device__ unsigned       g_doneB;

// ---------------- helpers ----------------
__device__ __forceinline__ float rcp_approx(float x) {
    float r; asm("rcp.approx.f32 %0, %1;" : "=f"(r) : "f"(x)); return r;
}
__device__ __forceinline__ float ex2a(float x) {
    float r; asm("ex2.approx.f32 %0, %1;" : "=f"(r) : "f"(x)); return r;
}
__device__ __forceinline__ float lg2a(float x) {
    float r; asm("lg2.approx.f32 %0, %1;" : "=f"(r) : "f"(x)); return r;
}
__device__ __forceinline__ float slctf(float a, float b, float c) {
    float r; asm("slct.f32.f32 %0, %1, %2, %3;" : "=f"(r) : "f"(a), "f"(b), "f"(c)); return r;
}
#define PK(d, a, b)    asm("mov.b64 %0, {%1, %2};" : "=l"(d) : "f"(a), "f"(b))
#define UPK(a, b, s)   asm("mov.b64 {%0, %1}, %2;" : "=f"(a), "=f"(b) : "l"(s))
#define F2MUL(d, a, b) asm("mul.rn.f32x2 %0, %1, %2;" : "=l"(d) : "l"(a), "l"(b))
#define F2ADD(d, a, b) asm("add.rn.f32x2 %0, %1, %2;" : "=l"(d) : "l"(a), "l"(b))
#define F2FMA(d, a, b, c) asm("fma.rn.f32x2 %0, %1, %2, %3;" : "=l"(d) : "l"(a), "l"(b), "l"(c))

struct PackK {
    unsigned long long SGN, ONE, TWO, M3, C3, C2, C1, C0;
};
__device__ __forceinline__ PackK make_packk() {
    PackK K;
    K.SGN = 0x8000000080000000ull;
    PK(K.ONE, 1.0f, 1.0f);
    PK(K.TWO, 2.0f, 2.0f);
    PK(K.M3, -3.0f, -3.0f);
    PK(K.C3, -0.028572f, -0.028572f);
    PK(K.C2,  0.08326f,   0.08326f);
    PK(K.C1, -0.22121f,  -0.22121f);
    PK(K.C0,  0.66548f,   0.66548f);
    return K;
}

// sum of p^2*softplus(l) over a packed pair; 2 MUFU + packed FMA work
__device__ __forceinline__ float pair_focal(float la, float lb, const PackK& K) {
    float t0 = ex2a(fabsf(la) * -1.44269504f);   // e^{-|l|}
    float t1 = ex2a(fabsf(lb) * -1.44269504f);
    unsigned long long T, U, X, R, NU, E, W, T2, V;
    PK(T, t0, t1);
    F2ADD(U, T, K.ONE);                          // u = 1 + t  in (1,2]
    float u0, u1; UPK(u0, u1, U);
    float lga = lg2a(u0), lgb = lg2a(u1);        // log2(u)
    F2FMA(X, U, K.TWO, K.M3);                    // x = 2u - 3 in [-1,1]
    F2FMA(R, K.C3, X, K.C2);                     // cubic seed for 1/u
    F2FMA(R, R, X, K.C1);
    F2FMA(R, R, X, K.C0);
    asm("xor.b64 %0, %1, %2;" : "=l"(NU) : "l"(U), "l"(K.SGN));
    F2FMA(E, NU, R, K.TWO);                      // 2 - u*r  (Newton)
    F2MUL(R, R, E);                              // r ~ 1/u
    F2MUL(W, R, R);                              // p^2 for l>=0
    F2MUL(T2, T, T);
    F2MUL(V, T2, W);                             // p^2 for l<0
    float w0, w1, v0, v1;
    UPK(w0, w1, W); UPK(v0, v1, V);
    float p20 = slctf(w0, v0, la);
    float p21 = slctf(w1, v1, lb);
    float ce0 = fmaf(lga, (float)LN2, fmaxf(la, 0.f));   // softplus(l)
    float ce1 = fmaf(lgb, (float)LN2, fmaxf(lb, 0.f));
    return fmaf(p20, ce0, p21 * ce1);
}

// ---------------- Launch A: fused stream focal + assignment ----------------
__global__ void __launch_bounds__(256, 4)
kA(const float4* __restrict__ anchors,
   const float4* __restrict__ bb,
   const float* __restrict__ y_true,
   const float4* __restrict__ yp4) {
    int bid = blockIdx.x;
    int tid = threadIdx.x;

    if (bid < SBX) {
        // ===== pure streaming focal over all elements (no state dependency) =====
        int n = bid / SBX_PER_N;
        int bx = bid - n * SBX_PER_N;
        const float4* yp = yp4 + (size_t)n * NFLT4 + bx * (256 * ITER);
        PackK K = make_packk();
        float clsl = 0.f;
        #pragma unroll
        for (int i = 0; i < ITER; i++) {
            float4 vv = yp[i * 256 + tid];
            clsl += pair_focal(vv.x, vv.y, K) + pair_focal(vv.z, vv.w, K);
        }
        // block reduce
        unsigned full = 0xFFFFFFFFu;
        #pragma unroll
        for (int o = 16; o > 0; o >>= 1)
            clsl += __shfl_down_sync(full, clsl, o);
        __shared__ float wc[8];
        int w = tid >> 5, lane = tid & 31;
        if (lane == 0) wc[w] = clsl;
        __syncthreads();
        if (tid == 0) {
            float c = 0.f;
            #pragma unroll
            for (int i = 0; i < 8; i++) c += wc[i];
            g_pcls[bid] = 0.75f * c;
        }
        return;
    }

    // ===== assignment (k1) =====
    int q = bid - SBX;
    int n = q >> 8;
    int axb = q & 255;

    __shared__ float4 sbox[Tt];
    __shared__ float  sarea[Tt];
    __shared__ unsigned char svt[Tt];
    __shared__ unsigned long long swkey[8][Tt];
    __shared__ unsigned smask[2];
    __shared__ int snv;

    float4 myb; bool myvalid = false; unsigned mk = 0;
    if (tid < 64) {
        myb = bb[n * Tt + tid];
        myvalid = (myb.x > 0.f) || (myb.y > 0.f) || (myb.z > 0.f) || (myb.w > 0.f);
        mk = __ballot_sync(0xFFFFFFFFu, myvalid);
        if ((tid & 31) == 0) smask[tid >> 5] = mk;
    }
    if (axb == 0 && tid >= 64 && tid < 128) {
        int r = n * Tt + (tid - 64);
        const float4* row = (const float4*)(y_true + (size_t)r * Cc);
        int lab = 0;
        #pragma unroll 4
        for (int qq = 0; qq < Cc / 4; qq++) {
            float4 v = row[qq];
            if (v.x > 0.5f) lab = 4 * qq;
            if (v.y > 0.5f) lab = 4 * qq + 1;
            if (v.z > 0.5f) lab = 4 * qq + 2;
            if (v.w > 0.5f) lab = 4 * qq + 3;
        }
        g_label[r] = (unsigned char)lab;
    }
    __syncthreads();
    if (tid < 64 && myvalid) {
        int pos = __popc(mk & ((1u << (tid & 31)) - 1)) +
                  ((tid >= 32) ? __popc(smask[0]) : 0);
        sbox[pos]  = myb;
        sarea[pos] = fmaxf(myb.z - myb.x, 0.f) * fmaxf(myb.w - myb.y, 0.f);
        svt[pos]   = (unsigned char)tid;
        if (axb == 0) g_vt[n * Tt + pos] = (unsigned char)tid;
    }
    if (tid == 0) {
        snv = __popc(smask[0]) + __popc(smask[1]);
        if (axb == 0) g_nvalid[n] = snv;
    }
    __syncthreads();
    int nv = snv;

    int a = axb * 256 + tid;
    float4 an = anchors[a];
    float a2 = fmaxf(an.z - an.x, 0.f) * fmaxf(an.w - an.y, 0.f);
    unsigned lane = tid & 31;
    int w = tid >> 5;

    float best = -1.0f; int arg = 0;
    for (int k = 0; k < nv; k++) {
        float4 b = sbox[k];
        float lx = fmaxf(b.x, an.x), ly = fmaxf(b.y, an.y);
        float rx = fminf(b.z, an.z), ry = fminf(b.w, an.w);
        float iw = fmaxf(rx - lx, 0.f), ih = fmaxf(ry - ly, 0.f);
        float inter = iw * ih;
        float uni = sarea[k] + a2 - inter;
        float iou = inter / fmaxf(uni, 1e-10f);       // exact div: thresholds flip-sensitive
        if (iou > best) { best = iou; arg = svt[k]; } // first-max (smallest t)

        unsigned ib = __float_as_uint(iou);
        unsigned mx = __reduce_max_sync(0xFFFFFFFFu, ib);
        unsigned msk = __ballot_sync(0xFFFFFFFFu, ib == mx);
        if (lane == (unsigned)(__ffs(msk) - 1))
            swkey[w][k] = ((unsigned long long)mx << 32) |
                          (unsigned long long)(~(unsigned)a);
    }
    __syncthreads();

    size_t idx = (size_t)n * Aa + a;
    g_asg[idx]   = arg;
    g_state[idx] = (best >= 0.5f) ? 2 : ((best < 0.4f) ? 1 : 0);

    if (tid < nv) {
        unsigned long long m = swkey[0][tid];
        #pragma unroll
        for (int ww = 1; ww < 8; ww++) {
            unsigned long long o = swkey[ww][tid];
            if (o > m) m = o;
        }
        if ((m >> 32) != 0)
            atomicMax(&g_gtkey[n * Tt + tid], m);
    }

    // fused low-quality override: last finishing assignment block applies all
    __syncthreads();
    __threadfence();
    __shared__ bool slast;
    if (tid == 0)
        slast = (atomicAdd(&g_done1, 1u) == (unsigned)(K1B - 1));
    __syncthreads();
    if (slast) {
        for (int idx2 = tid; idx2 < Nn * Tt; idx2 += 256) {
            int nn = idx2 >> 6, k = idx2 & 63;
            if (k < g_nvalid[nn]) {
                unsigned long long key = g_gtkey[nn * Tt + k];
                if ((key >> 32) != 0) {
                    int aa = (int)(~(unsigned)(key & 0xFFFFFFFFull));
                    int t = g_vt[nn * Tt + k];
                    size_t p = (size_t)nn * Aa + aa;
                    atomicMax(&g_asg[p], 0x40000000 | t);
                    g_state[p] = 2;
                }
            }
        }
    }
}

// ---------------- Launch B: corrections (ignore subtract, pos fixup+box) + finalize ----------------
__global__ void __launch_bounds__(256)
kB(const float4* __restrict__ yp4,
   const float4* __restrict__ anchors,
   const float4* __restrict__ bbp4,
   const float* __restrict__ bbox_true,
   float* __restrict__ out) {
    PackK K = make_packk();
    float cls = 0.f, box = 0.f;
    int gtid = blockIdx.x * 256 + threadIdx.x;

    for (int idx = gtid; idx < Nn * Aa; idx += QB * 256) {
        unsigned st = g_state[idx];
        if (st == 1) continue;
        int n = idx >> 16;
        int a = idx & (Aa - 1);
        const float4* yp = yp4 + (size_t)n * NFLT4 + (size_t)a * 20;

        if (st == 0) {
            // ignore anchor: subtract its streamed focal sum (same formula)
            float S = 0.f;
            #pragma unroll 4
            for (int qq = 0; qq < 20; qq++) {
                float4 vv = yp[qq];
                S += pair_focal(vv.x, vv.y, K) + pair_focal(vv.z, vv.w, K);
            }
            cls -= 0.75f * S;
        } else {
            // positive anchor
            atomicAdd(&g_poscnt[n], 1);
            int v = g_asg[idx];
            int asg = (v & 0x40000000) ? (v & 0xFF) : v;
            int label = (int)g_label[n * Tt + asg];
            float4 vv = yp[label >> 2];
            int j = label & 3;
            float lsel = (j == 0) ? vv.x : ((j == 1) ? vv.y : ((j == 2) ? vv.z : vv.w));
            {
                float mm = fabsf(lsel);
                float em = __expf(-mm);
                float uu = 1.0f + em;
                float r  = rcp_approx(uu);
                float lgv = __logf(uu);
                float p  = (lsel >= 0.f) ? r : em * r;
                float qd = 1.0f - p;
                float ce  = lgv + fmaxf(lsel, 0.f);   // softplus(l)
                float cep = lgv + fmaxf(-lsel, 0.f);  // softplus(-l)
                cls += 0.25f * qd * qd * cep - 0.75f * p * p * ce;
            }
            // box loss
            float4 an = anchors[a];
            float4 bp = bbp4[idx];
            const float* bt = bbox_true + ((size_t)n * Tt + asg) * 4;
            float bx1 = bt[0], by1 = bt[1], bx2 = bt[2], by2 = bt[3];
            float wa = fmaxf(an.z - an.x, F_EPS);
            float ha = fmaxf(an.w - an.y, F_EPS);
            float cxa = an.x + 0.5f * wa;
            float cya = an.y + 0.5f * ha;
            float wt = fmaxf(bx2 - bx1, F_EPS);
            float ht = fmaxf(by2 - by1, F_EPS);
            float cxt = bx1 + 0.5f * (bx2 - bx1);
            float cyt = by1 + 0.5f * (by2 - by1);
            float tg0 = (cxt - cxa) / wa;
            float tg1 = (cyt - cya) / ha;
            float tg2 = logf(wt / wa);
            float tg3 = logf(ht / ha);
            float d0 = fabsf(tg0 - bp.x), d1 = fabsf(tg1 - bp.y);
            float d2 = fabsf(tg2 - bp.z), d3 = fabsf(tg3 - bp.w);
            box += (d0 < SL1_BETA) ? (0.5f * d0 * d0 / SL1_BETA) : (d0 - 0.5f * SL1_BETA);
            box += (d1 < SL1_BETA) ? (0.5f * d1 * d1 / SL1_BETA) : (d1 - 0.5f * SL1_BETA);
            box += (d2 < SL1_BETA) ? (0.5f * d2 * d2 / SL1_BETA) : (d2 - 0.5f * SL1_BETA);
            box += (d3 < SL1_BETA) ? (0.5f * d3 * d3 / SL1_BETA) : (d3 - 0.5f * SL1_BETA);
        }
    }

    // block reduce
    unsigned full = 0xFFFFFFFFu;
    #pragma unroll
    for (int o = 16; o > 0; o >>= 1) {
        cls += __shfl_down_sync(full, cls, o);
        box += __shfl_down_sync(full, box, o);
    }
    __shared__ float wc[8], wb[8];
    int w = threadIdx.x >> 5, lane = threadIdx.x & 31;
    if (lane == 0) { wc[w] = cls; wb[w] = box; }
    __syncthreads();
    if (threadIdx.x == 0) {
        float c = 0.f, b = 0.f;
        #pragma unroll
        for (int i = 0; i < 8; i++) { c += wc[i]; b += wb[i]; }
        g_qcls[blockIdx.x] = c;
        g_qbox[blockIdx.x] = b;
    }

    // last finishing block: final reduce + output + resets
    __syncthreads();
    __threadfence();
    __shared__ bool slast;
    if (threadIdx.x == 0)
        slast = (atomicAdd(&g_doneB, 1u) == (unsigned)(QB - 1));
    __syncthreads();
    if (!slast) return;

    __shared__ double sc[256], sb2[256];
    int tid = threadIdx.x;
    double c = 0.0, b = 0.0;
    for (int i = tid; i < SBX; i += 256) c += (double)g_pcls[i];
    if (tid < QB) { c += (double)g_qcls[tid]; b += (double)g_qbox[tid]; }
    sc[tid] = c; sb2[tid] = b;
    __syncthreads();
    for (int s = 128; s > 0; s >>= 1) {
        if (tid < s) { sc[tid] += sc[tid + s]; sb2[tid] += sb2[tid + s]; }
        __syncthreads();
    }
    if (tid == 0) {
        double avg = 0.0;
        for (int nn = 0; nn < Nn; nn++) {
            double p = (double)g_poscnt[nn];
            avg += (p > 1.0) ? p : 1.0;
        }
        float clsO = (float)(sc[0] / avg);
        float boxO = (float)(sb2[0] / avg);
        if (isnan(clsO) || isinf(clsO)) clsO = 0.f;
        if (isnan(boxO) || isinf(boxO)) boxO = 0.f;
        out[0] = clsO;
        out[1] = boxO;
    }
    // resets for next graph replay
    __syncthreads();
    if (tid == 0) { g_done1 = 0; g_doneB = 0; }
    if (tid < Nn) g_poscnt[tid] = 0;
    for (int i = tid; i < Nn * Tt; i += 256) g_gtkey[i] = 0ull;
}

// ---------------- launch ----------------
extern "C" void kernel_launch(void* const* d_in, const int* in_sizes, int n_in,
                              void* d_out, int out_size) {
    const float*  y_true    = (const float*)d_in[0];
    const float*  bbox_true = (const float*)d_in[1];
    const float*  y_pred    = (const float*)d_in[2];
    const float4* bbox_pred = (const float4*)d_in[3];
    const float4* anchors   = (const float4*)d_in[4];
    float* out = (float*)d_out;

    kA<<<TOTB, 256>>>(anchors, (const float4*)bbox_true, y_true,
                      (const float4*)y_pred);
    kB<<<QB, 256>>>((const float4*)y_pred, anchors, bbox_pred, bbox_true, out);
}

// round 8
// speedup vs baseline: 2.3298x; 2.3298x over previous
#include <cuda_runtime.h>
#include <math.h>

#define Nn 8
#define Tt 64
#define Aa 65536
#define Cc 80
#define NFLT4 (Aa * (Cc / 4))          // float4s of y_pred per image = 1,310,720
#define ITER 8
#define SBX_PER_N 640                   // stream blocks per image
#define SBX (SBX_PER_N * Nn)            // 5120
#define K1B ((Aa / 256) * Nn)           // 2048
#define TOTB (SBX + K1B)                // 7168
#define QB 512                          // correction blocks

#define F_EPS 1e-6f
#define SL1_BETA (1.0f / 9.0f)
#define LN2 0.69314718055994531f

// ---------------- scratch (device globals; no allocation) ----------------
__device__ int            g_state[Nn * Aa];   // 0=ignore 1=neg 2=pos (int for atomics)
__device__ int            g_asg[Nn * Aa];     // bit30 = override, low bits = gt index t
__device__ int            g_nvalid[Nn];
__device__ unsigned char  g_vt[Nn * Tt];
__device__ unsigned char  g_label[Nn * Tt];
__device__ unsigned long long g_gtkey[Nn * Tt];
__device__ int            g_poscnt[Nn];
__device__ float          g_pcls[SBX];
__device__ float          g_qcls[QB];
__device__ float          g_qbox[QB];
__device__ int            g_ignlist[Nn * Aa];
__device__ int            g_poslist[Nn * Aa];
__device__ int            g_nign;
__device__ int            g_npos;
__device__ unsigned       g_done1;
__device__ unsigned       g_doneB;

// ---------------- helpers ----------------
__device__ __forceinline__ float rcp_approx(float x) {
    float r; asm("rcp.approx.f32 %0, %1;" : "=f"(r) : "f"(x)); return r;
}
__device__ __forceinline__ float ex2a(float x) {
    float r; asm("ex2.approx.f32 %0, %1;" : "=f"(r) : "f"(x)); return r;
}
__device__ __forceinline__ float lg2a(float x) {
    float r; asm("lg2.approx.f32 %0, %1;" : "=f"(r) : "f"(x)); return r;
}
__device__ __forceinline__ float slctf(float a, float b, float c) {
    float r; asm("slct.f32.f32 %0, %1, %2, %3;" : "=f"(r) : "f"(a), "f"(b), "f"(c)); return r;
}
#define PK(d, a, b)    asm("mov.b64 %0, {%1, %2};" : "=l"(d) : "f"(a), "f"(b))
#define UPK(a, b, s)   asm("mov.b64 {%0, %1}, %2;" : "=f"(a), "=f"(b) : "l"(s))
#define F2MUL(d, a, b) asm("mul.rn.f32x2 %0, %1, %2;" : "=l"(d) : "l"(a), "l"(b))
#define F2ADD(d, a, b) asm("add.rn.f32x2 %0, %1, %2;" : "=l"(d) : "l"(a), "l"(b))
#define F2FMA(d, a, b, c) asm("fma.rn.f32x2 %0, %1, %2, %3;" : "=l"(d) : "l"(a), "l"(b), "l"(c))

struct PackK {
    unsigned long long SGN, ONE, TWO, M3, C3, C2, C1, C0;
};
__device__ __forceinline__ PackK make_packk() {
    PackK K;
    K.SGN = 0x8000000080000000ull;
    PK(K.ONE, 1.0f, 1.0f);
    PK(K.TWO, 2.0f, 2.0f);
    PK(K.M3, -3.0f, -3.0f);
    PK(K.C3, -0.028572f, -0.028572f);
    PK(K.C2,  0.08326f,   0.08326f);
    PK(K.C1, -0.22121f,  -0.22121f);
    PK(K.C0,  0.66548f,   0.66548f);
    return K;
}

// sum of p^2*softplus(l) over a packed pair; 2 MUFU + packed FMA work
__device__ __forceinline__ float pair_focal(float la, float lb, const PackK& K) {
    float t0 = ex2a(fabsf(la) * -1.44269504f);   // e^{-|l|}
    float t1 = ex2a(fabsf(lb) * -1.44269504f);
    unsigned long long T, U, X, R, NU, E, W, T2, V;
    PK(T, t0, t1);
    F2ADD(U, T, K.ONE);                          // u = 1 + t  in (1,2]
    float u0, u1; UPK(u0, u1, U);
    float lga = lg2a(u0), lgb = lg2a(u1);        // log2(u)
    F2FMA(X, U, K.TWO, K.M3);                    // x = 2u - 3 in [-1,1]
    F2FMA(R, K.C3, X, K.C2);                     // cubic seed for 1/u
    F2FMA(R, R, X, K.C1);
    F2FMA(R, R, X, K.C0);
    asm("xor.b64 %0, %1, %2;" : "=l"(NU) : "l"(U), "l"(K.SGN));
    F2FMA(E, NU, R, K.TWO);                      // 2 - u*r  (Newton)
    F2MUL(R, R, E);                              // r ~ 1/u
    F2MUL(W, R, R);                              // p^2 for l>=0
    F2MUL(T2, T, T);
    F2MUL(V, T2, W);                             // p^2 for l<0
    float w0, w1, v0, v1;
    UPK(w0, w1, W); UPK(v0, v1, V);
    float p20 = slctf(w0, v0, la);
    float p21 = slctf(w1, v1, lb);
    float ce0 = fmaf(lga, (float)LN2, fmaxf(la, 0.f));   // softplus(l)
    float ce1 = fmaf(lgb, (float)LN2, fmaxf(lb, 0.f));
    return fmaf(p20, ce0, p21 * ce1);
}

// ---------------- Launch A: fused stream focal + assignment + list build ----------------
__global__ void __launch_bounds__(256, 4)
kA(const float4* __restrict__ anchors,
   const float4* __restrict__ bb,
   const float* __restrict__ y_true,
   const float4* __restrict__ yp4) {
    int bid = blockIdx.x;
    int tid = threadIdx.x;

    if (bid < SBX) {
        // ===== pure streaming focal over all elements =====
        int n = bid / SBX_PER_N;
        int bx = bid - n * SBX_PER_N;
        const float4* yp = yp4 + (size_t)n * NFLT4 + bx * (256 * ITER);
        PackK K = make_packk();
        float clsl = 0.f;
        #pragma unroll
        for (int i = 0; i < ITER; i++) {
            float4 vv = yp[i * 256 + tid];
            clsl += pair_focal(vv.x, vv.y, K) + pair_focal(vv.z, vv.w, K);
        }
        unsigned full = 0xFFFFFFFFu;
        #pragma unroll
        for (int o = 16; o > 0; o >>= 1)
            clsl += __shfl_down_sync(full, clsl, o);
        __shared__ float wc[8];
        int w = tid >> 5, lane = tid & 31;
        if (lane == 0) wc[w] = clsl;
        __syncthreads();
        if (tid == 0) {
            float c = 0.f;
            #pragma unroll
            for (int i = 0; i < 8; i++) c += wc[i];
            g_pcls[bid] = 0.75f * c;
        }
        return;
    }

    // ===== assignment =====
    int q = bid - SBX;
    int n = q >> 8;
    int axb = q & 255;

    __shared__ float4 sbox[Tt];
    __shared__ float  sarea[Tt];
    __shared__ unsigned char svt[Tt];
    __shared__ unsigned long long swkey[8][Tt];
    __shared__ unsigned smask[2];
    __shared__ int snv;

    float4 myb; bool myvalid = false; unsigned mk = 0;
    if (tid < 64) {
        myb = bb[n * Tt + tid];
        myvalid = (myb.x > 0.f) || (myb.y > 0.f) || (myb.z > 0.f) || (myb.w > 0.f);
        mk = __ballot_sync(0xFFFFFFFFu, myvalid);
        if ((tid & 31) == 0) smask[tid >> 5] = mk;
    }
    if (axb == 0 && tid >= 64 && tid < 128) {
        int r = n * Tt + (tid - 64);
        const float4* row = (const float4*)(y_true + (size_t)r * Cc);
        int lab = 0;
        #pragma unroll 4
        for (int qq = 0; qq < Cc / 4; qq++) {
            float4 v = row[qq];
            if (v.x > 0.5f) lab = 4 * qq;
            if (v.y > 0.5f) lab = 4 * qq + 1;
            if (v.z > 0.5f) lab = 4 * qq + 2;
            if (v.w > 0.5f) lab = 4 * qq + 3;
        }
        g_label[r] = (unsigned char)lab;
    }
    __syncthreads();
    if (tid < 64 && myvalid) {
        int pos = __popc(mk & ((1u << (tid & 31)) - 1)) +
                  ((tid >= 32) ? __popc(smask[0]) : 0);
        sbox[pos]  = myb;
        sarea[pos] = fmaxf(myb.z - myb.x, 0.f) * fmaxf(myb.w - myb.y, 0.f);
        svt[pos]   = (unsigned char)tid;
        if (axb == 0) g_vt[n * Tt + pos] = (unsigned char)tid;
    }
    if (tid == 0) {
        snv = __popc(smask[0]) + __popc(smask[1]);
        if (axb == 0) g_nvalid[n] = snv;
    }
    __syncthreads();
    int nv = snv;

    int a = axb * 256 + tid;
    float4 an = anchors[a];
    float a2 = fmaxf(an.z - an.x, 0.f) * fmaxf(an.w - an.y, 0.f);
    unsigned lane = tid & 31;
    int w = tid >> 5;

    float best = -1.0f; int arg = 0;
    for (int k = 0; k < nv; k++) {
        float4 b = sbox[k];
        float lx = fmaxf(b.x, an.x), ly = fmaxf(b.y, an.y);
        float rx = fminf(b.z, an.z), ry = fminf(b.w, an.w);
        float iw = fmaxf(rx - lx, 0.f), ih = fmaxf(ry - ly, 0.f);
        float inter = iw * ih;
        float uni = sarea[k] + a2 - inter;
        float iou = inter / fmaxf(uni, 1e-10f);       // exact div: thresholds flip-sensitive
        if (iou > best) { best = iou; arg = svt[k]; } // first-max (smallest t)

        unsigned ib = __float_as_uint(iou);
        unsigned mx = __reduce_max_sync(0xFFFFFFFFu, ib);
        unsigned msk = __ballot_sync(0xFFFFFFFFu, ib == mx);
        if (lane == (unsigned)(__ffs(msk) - 1))
            swkey[w][k] = ((unsigned long long)mx << 32) |
                          (unsigned long long)(~(unsigned)a);
    }
    __syncthreads();

    int idx = n * Aa + a;
    int st = (best >= 0.5f) ? 2 : ((best < 0.4f) ? 1 : 0);
    g_asg[idx]   = arg;
    g_state[idx] = st;

    // warp-aggregated list appends
    {
        unsigned bpos = __ballot_sync(0xFFFFFFFFu, st == 2);
        unsigned bign = __ballot_sync(0xFFFFFFFFu, st == 0);
        unsigned lmask = (1u << lane) - 1u;
        int basep = 0, basei = 0;
        if (lane == 0) {
            if (bpos) {
                basep = atomicAdd(&g_npos, __popc(bpos));
                atomicAdd(&g_poscnt[n], __popc(bpos));
            }
            if (bign) basei = atomicAdd(&g_nign, __popc(bign));
        }
        basep = __shfl_sync(0xFFFFFFFFu, basep, 0);
        basei = __shfl_sync(0xFFFFFFFFu, basei, 0);
        if (st == 2) g_poslist[basep + __popc(bpos & lmask)] = idx;
        if (st == 0) g_ignlist[basei + __popc(bign & lmask)] = idx;
    }

    if (tid < nv) {
        unsigned long long m = swkey[0][tid];
        #pragma unroll
        for (int ww = 1; ww < 8; ww++) {
            unsigned long long o = swkey[ww][tid];
            if (o > m) m = o;
        }
        if ((m >> 32) != 0)
            atomicMax(&g_gtkey[n * Tt + tid], m);
    }

    // fused low-quality override: last finishing assignment block applies all
    __syncthreads();
    __threadfence();
    __shared__ bool slast;
    if (tid == 0)
        slast = (atomicAdd(&g_done1, 1u) == (unsigned)(K1B - 1));
    __syncthreads();
    if (slast) {
        for (int idx2 = tid; idx2 < Nn * Tt; idx2 += 256) {
            int nn = idx2 >> 6, k = idx2 & 63;
            if (k < g_nvalid[nn]) {
                unsigned long long key = g_gtkey[nn * Tt + k];
                if ((key >> 32) != 0) {
                    int aa = (int)(~(unsigned)(key & 0xFFFFFFFFull));
                    int t = g_vt[nn * Tt + k];
                    int p = nn * Aa + aa;
                    atomicMax(&g_asg[p], 0x40000000 | t);
                    int old = atomicExch(&g_state[p], 2);
                    if (old != 2) {
                        int pp = atomicAdd(&g_npos, 1);
                        g_poslist[pp] = p;
                        atomicAdd(&g_poscnt[nn], 1);
                    }
                }
            }
        }
    }
}

// ---------------- Launch B: list-driven corrections + finalize ----------------
__global__ void __launch_bounds__(256)
kB(const float4* __restrict__ yp4,
   const float4* __restrict__ anchors,
   const float4* __restrict__ bbp4,
   const float* __restrict__ bbox_true,
   float* __restrict__ out) {
    PackK K = make_packk();
    float cls = 0.f, box = 0.f;
    int gtid = blockIdx.x * 256 + threadIdx.x;
    const int stride = QB * 256;

    // ---- ignore subtraction: one work item = (entry, float4-q) ----
    int nI = g_nign;
    for (int it = gtid; it < nI * 20; it += stride) {
        int e = it / 20;
        int qq = it - e * 20;
        int idx = g_ignlist[e];
        if (g_state[idx] != 0) continue;            // LQ promoted it to pos
        int n = idx >> 16;
        int a = idx & (Aa - 1);
        float4 vv = yp4[(size_t)n * NFLT4 + (size_t)a * 20 + qq];
        cls -= 0.75f * (pair_focal(vv.x, vv.y, K) + pair_focal(vv.z, vv.w, K));
    }

    // ---- positive corrections: one work item = one pos anchor ----
    int nP = g_npos;
    for (int e = gtid; e < nP; e += stride) {
        int idx = g_poslist[e];
        int n = idx >> 16;
        int a = idx & (Aa - 1);
        const float4* yp = yp4 + (size_t)n * NFLT4 + (size_t)a * 20;
        int v = g_asg[idx];
        int asg = (v & 0x40000000) ? (v & 0xFF) : v;
        int label = (int)g_label[n * Tt + asg];
        float4 vv = yp[label >> 2];
        int j = label & 3;
        float lsel = (j == 0) ? vv.x : ((j == 1) ? vv.y : ((j == 2) ? vv.z : vv.w));
        {
            float mm = fabsf(lsel);
            float em = __expf(-mm);
            float uu = 1.0f + em;
            float r  = rcp_approx(uu);
            float lgv = __logf(uu);
            float p  = (lsel >= 0.f) ? r : em * r;
            float qd = 1.0f - p;
            float ce  = lgv + fmaxf(lsel, 0.f);
            float cep = lgv + fmaxf(-lsel, 0.f);
            cls += 0.25f * qd * qd * cep - 0.75f * p * p * ce;
        }
        float4 an = anchors[a];
        float4 bp = bbp4[idx];
        const float* bt = bbox_true + ((size_t)n * Tt + asg) * 4;
        float bx1 = bt[0], by1 = bt[1], bx2 = bt[2], by2 = bt[3];
        float wa = fmaxf(an.z - an.x, F_EPS);
        float ha = fmaxf(an.w - an.y, F_EPS);
        float cxa = an.x + 0.5f * wa;
        float cya = an.y + 0.5f * ha;
        float wt = fmaxf(bx2 - bx1, F_EPS);
        float ht = fmaxf(by2 - by1, F_EPS);
        float cxt = bx1 + 0.5f * (bx2 - bx1);
        float cyt = by1 + 0.5f * (by2 - by1);
        float tg0 = (cxt - cxa) / wa;
        float tg1 = (cyt - cya) / ha;
        float tg2 = logf(wt / wa);
        float tg3 = logf(ht / ha);
        float d0 = fabsf(tg0 - bp.x), d1 = fabsf(tg1 - bp.y);
        float d2 = fabsf(tg2 - bp.z), d3 = fabsf(tg3 - bp.w);
        box += (d0 < SL1_BETA) ? (0.5f * d0 * d0 / SL1_BETA) : (d0 - 0.5f * SL1_BETA);
        box += (d1 < SL1_BETA) ? (0.5f * d1 * d1 / SL1_BETA) : (d1 - 0.5f * SL1_BETA);
        box += (d2 < SL1_BETA) ? (0.5f * d2 * d2 / SL1_BETA) : (d2 - 0.5f * SL1_BETA);
        box += (d3 < SL1_BETA) ? (0.5f * d3 * d3 / SL1_BETA) : (d3 - 0.5f * SL1_BETA);
    }

    // block reduce
    unsigned full = 0xFFFFFFFFu;
    #pragma unroll
    for (int o = 16; o > 0; o >>= 1) {
        cls += __shfl_down_sync(full, cls, o);
        box += __shfl_down_sync(full, box, o);
    }
    __shared__ float wc[8], wb[8];
    int w = threadIdx.x >> 5, lane = threadIdx.x & 31;
    if (lane == 0) { wc[w] = cls; wb[w] = box; }
    __syncthreads();
    if (threadIdx.x == 0) {
        float c = 0.f, b = 0.f;
        #pragma unroll
        for (int i = 0; i < 8; i++) { c += wc[i]; b += wb[i]; }
        g_qcls[blockIdx.x] = c;
        g_qbox[blockIdx.x] = b;
    }

    // last finishing block: final reduce + output + resets
    __syncthreads();
    __threadfence();
    __shared__ bool slast;
    if (threadIdx.x == 0)
        slast = (atomicAdd(&g_doneB, 1u) == (unsigned)(QB - 1));
    __syncthreads();
    if (!slast) return;

    __shared__ double sc[256], sb2[256];
    int tid = threadIdx.x;
    double c = 0.0, b = 0.0;
    for (int i = tid; i < SBX; i += 256) c += (double)g_pcls[i];
    for (int i = tid; i < QB; i += 256) { c += (double)g_qcls[i]; b += (double)g_qbox[i]; }
    sc[tid] = c; sb2[tid] = b;
    __syncthreads();
    for (int s = 128; s > 0; s >>= 1) {
        if (tid < s) { sc[tid] += sc[tid + s]; sb2[tid] += sb2[tid + s]; }
        __syncthreads();
    }
    if (tid == 0) {
        double avg = 0.0;
        for (int nn = 0; nn < Nn; nn++) {
            double p = (double)g_poscnt[nn];
            avg += (p > 1.0) ? p : 1.0;
        }
        float clsO = (float)(sc[0] / avg);
        float boxO = (float)(sb2[0] / avg);
        if (isnan(clsO) || isinf(clsO)) clsO = 0.f;
        if (isnan(boxO) || isinf(boxO)) boxO = 0.f;
        out[0] = clsO;
        out[1] = boxO;
    }
    // resets for next graph replay
    __syncthreads();
    if (tid == 0) { g_done1 = 0; g_doneB = 0; g_npos = 0; g_nign = 0; }
    if (tid < Nn) g_poscnt[tid] = 0;
    for (int i = tid; i < Nn * Tt; i += 256) g_gtkey[i] = 0ull;
}

// ---------------- launch ----------------
extern "C" void kernel_launch(void* const* d_in, const int* in_sizes, int n_in,
                              void* d_out, int out_size) {
    const float*  y_true    = (const float*)d_in[0];
    const float*  bbox_true = (const float*)d_in[1];
    const float*  y_pred    = (const float*)d_in[2];
    const float4* bbox_pred = (const float4*)d_in[3];
    const float4* anchors   = (const float4*)d_in[4];
    float* out = (float*)d_out;

    kA<<<TOTB, 256>>>(anchors, (const float4*)bbox_true, y_true,
                      (const float4*)y_pred);
    kB<<<QB, 256>>>((const float4*)y_pred, anchors, bbox_pred, bbox_true, out);
}

// round 9
// speedup vs baseline: 2.4392x; 1.0470x over previous
#include <cuda_runtime.h>
#include <math.h>

#define Nn 8
#define Tt 64
#define Aa 65536
#define Cc 80
#define NFLT4 (Aa * (Cc / 4))          // float4s of y_pred per image = 1,310,720
#define ITER 8
#define SBX_PER_N 640                   // stream blocks per image
#define SBX (SBX_PER_N * Nn)            // 5120
#define K1B ((Aa / 256) * Nn)           // 2048
#define TOTB (SBX + K1B)                // 7168
#define QB 2048                         // correction blocks

#define F_EPS 1e-6f
#define SL1_BETA (1.0f / 9.0f)
#define LN2 0.69314718055994531f

// ---------------- scratch (device globals; no allocation) ----------------
__device__ int            g_state[Nn * Aa];   // 0=ignore 1=neg 2=pos
__device__ int            g_asg[Nn * Aa];     // bit30 = override, low bits = gt index t
__device__ int            g_nvalid[Nn];
__device__ unsigned char  g_vt[Nn * Tt];
__device__ unsigned char  g_label[Nn * Tt];
__device__ unsigned long long g_gtkey[Nn * Tt];
__device__ int            g_poscnt[Nn];
__device__ float          g_pcls[SBX];
__device__ float          g_qcls[QB];
__device__ float          g_qbox[QB];
__device__ int            g_ignlist[Nn * Aa];
__device__ int            g_poslist[Nn * Aa];
__device__ int            g_nign;
__device__ int            g_npos;
__device__ unsigned       g_done1;
__device__ unsigned       g_doneB;

// ---------------- helpers ----------------
__device__ __forceinline__ float rcp_approx(float x) {
    float r; asm("rcp.approx.f32 %0, %1;" : "=f"(r) : "f"(x)); return r;
}
__device__ __forceinline__ float ex2a(float x) {
    float r; asm("ex2.approx.f32 %0, %1;" : "=f"(r) : "f"(x)); return r;
}
__device__ __forceinline__ float lg2a(float x) {
    float r; asm("lg2.approx.f32 %0, %1;" : "=f"(r) : "f"(x)); return r;
}
__device__ __forceinline__ float slctf(float a, float b, float c) {
    float r; asm("slct.f32.f32 %0, %1, %2, %3;" : "=f"(r) : "f"(a), "f"(b), "f"(c)); return r;
}

// p^2 * softplus(l): 2 MUFU (EX2, LG2) + pure-FMA Newton reciprocal; scalar,
// straight-line -> ptxas schedules freely.
__device__ __forceinline__ float focal_elem(float l) {
    float t  = ex2a(fabsf(l) * -1.44269504f);   // e^{-|l|} in (0,1]
    float u  = 1.0f + t;                         // (1,2]
    float x  = fmaf(2.0f, u, -3.0f);             // [-1,1]
    float r  = fmaf(-0.028572f, x, 0.08326f);    // cubic seed for 1/u
    r = fmaf(r, x, -0.22121f);
    r = fmaf(r, x, 0.66548f);
    r = r * fmaf(-u, r, 2.0f);                   // Newton: rel err ~2e-6
    float w  = r * r;                            // p^2 for l>=0
    float tr = t * r;
    float v  = tr * tr;                          // p^2 for l<0
    float p2 = slctf(w, v, l);
    float ce = fmaf(lg2a(u), (float)LN2, fmaxf(l, 0.f)); // softplus(l)
    return p2 * ce;
}

// ---------------- Launch A: assignment blocks FIRST, then stream focal ----------------
__global__ void __launch_bounds__(256, 4)
kA(const float4* __restrict__ anchors,
   const float4* __restrict__ bb,
   const float* __restrict__ y_true,
   const float4* __restrict__ yp4) {
    int bid = blockIdx.x;
    int tid = threadIdx.x;

    if (bid >= K1B) {
        // ===== pure streaming focal over all elements =====
        int sb = bid - K1B;
        int n = sb / SBX_PER_N;
        int bx = sb - n * SBX_PER_N;
        const float4* yp = yp4 + (size_t)n * NFLT4 + bx * (256 * ITER);
        float clsl = 0.f;
        #pragma unroll
        for (int i = 0; i < ITER; i++) {
            float4 vv = yp[i * 256 + tid];
            clsl += focal_elem(vv.x) + focal_elem(vv.y) +
                    focal_elem(vv.z) + focal_elem(vv.w);
        }
        unsigned full = 0xFFFFFFFFu;
        #pragma unroll
        for (int o = 16; o > 0; o >>= 1)
            clsl += __shfl_down_sync(full, clsl, o);
        __shared__ float wc[8];
        int w = tid >> 5, lane = tid & 31;
        if (lane == 0) wc[w] = clsl;
        __syncthreads();
        if (tid == 0) {
            float c = 0.f;
            #pragma unroll
            for (int i = 0; i < 8; i++) c += wc[i];
            g_pcls[sb] = 0.75f * c;
        }
        return;
    }

    // ===== assignment =====
    int q = bid;
    int n = q >> 8;
    int axb = q & 255;

    __shared__ float4 sbox[Tt];
    __shared__ float  sarea[Tt];
    __shared__ unsigned char svt[Tt];
    __shared__ unsigned long long swkey[8][Tt];
    __shared__ unsigned smask[2];
    __shared__ int snv;

    float4 myb; bool myvalid = false; unsigned mk = 0;
    if (tid < 64) {
        myb = bb[n * Tt + tid];
        myvalid = (myb.x > 0.f) || (myb.y > 0.f) || (myb.z > 0.f) || (myb.w > 0.f);
        mk = __ballot_sync(0xFFFFFFFFu, myvalid);
        if ((tid & 31) == 0) smask[tid >> 5] = mk;
    }
    if (axb == 0 && tid >= 64 && tid < 128) {
        int r = n * Tt + (tid - 64);
        const float4* row = (const float4*)(y_true + (size_t)r * Cc);
        int lab = 0;
        #pragma unroll 4
        for (int qq = 0; qq < Cc / 4; qq++) {
            float4 v = row[qq];
            if (v.x > 0.5f) lab = 4 * qq;
            if (v.y > 0.5f) lab = 4 * qq + 1;
            if (v.z > 0.5f) lab = 4 * qq + 2;
            if (v.w > 0.5f) lab = 4 * qq + 3;
        }
        g_label[r] = (unsigned char)lab;
    }
    __syncthreads();
    if (tid < 64 && myvalid) {
        int pos = __popc(mk & ((1u << (tid & 31)) - 1)) +
                  ((tid >= 32) ? __popc(smask[0]) : 0);
        sbox[pos]  = myb;
        sarea[pos] = fmaxf(myb.z - myb.x, 0.f) * fmaxf(myb.w - myb.y, 0.f);
        svt[pos]   = (unsigned char)tid;
        if (axb == 0) g_vt[n * Tt + pos] = (unsigned char)tid;
    }
    if (tid == 0) {
        snv = __popc(smask[0]) + __popc(smask[1]);
        if (axb == 0) g_nvalid[n] = snv;
    }
    __syncthreads();
    int nv = snv;

    int a = axb * 256 + tid;
    float4 an = anchors[a];
    float a2 = fmaxf(an.z - an.x, 0.f) * fmaxf(an.w - an.y, 0.f);
    unsigned lane = tid & 31;
    int w = tid >> 5;

    float best = -1.0f; int arg = 0;
    for (int k = 0; k < nv; k++) {
        float4 b = sbox[k];
        float lx = fmaxf(b.x, an.x), ly = fmaxf(b.y, an.y);
        float rx = fminf(b.z, an.z), ry = fminf(b.w, an.w);
        float iw = fmaxf(rx - lx, 0.f), ih = fmaxf(ry - ly, 0.f);
        float inter = iw * ih;
        float uni = sarea[k] + a2 - inter;
        float iou = inter / fmaxf(uni, 1e-10f);       // exact div: thresholds flip-sensitive
        if (iou > best) { best = iou; arg = svt[k]; } // first-max (smallest t)

        unsigned ib = __float_as_uint(iou);
        unsigned mx = __reduce_max_sync(0xFFFFFFFFu, ib);
        unsigned msk = __ballot_sync(0xFFFFFFFFu, ib == mx);
        if (lane == (unsigned)(__ffs(msk) - 1))
            swkey[w][k] = ((unsigned long long)mx << 32) |
                          (unsigned long long)(~(unsigned)a);
    }
    __syncthreads();

    int idx = n * Aa + a;
    int st = (best >= 0.5f) ? 2 : ((best < 0.4f) ? 1 : 0);
    g_asg[idx]   = arg;
    g_state[idx] = st;

    // warp-aggregated list appends
    {
        unsigned bpos = __ballot_sync(0xFFFFFFFFu, st == 2);
        unsigned bign = __ballot_sync(0xFFFFFFFFu, st == 0);
        unsigned lmask = (1u << lane) - 1u;
        int basep = 0, basei = 0;
        if (lane == 0) {
            if (bpos) {
                basep = atomicAdd(&g_npos, __popc(bpos));
                atomicAdd(&g_poscnt[n], __popc(bpos));
            }
            if (bign) basei = atomicAdd(&g_nign, __popc(bign));
        }
        basep = __shfl_sync(0xFFFFFFFFu, basep, 0);
        basei = __shfl_sync(0xFFFFFFFFu, basei, 0);
        if (st == 2) g_poslist[basep + __popc(bpos & lmask)] = idx;
        if (st == 0) g_ignlist[basei + __popc(bign & lmask)] = idx;
    }

    if (tid < nv) {
        unsigned long long m = swkey[0][tid];
        #pragma unroll
        for (int ww = 1; ww < 8; ww++) {
            unsigned long long o = swkey[ww][tid];
            if (o > m) m = o;
        }
        if ((m >> 32) != 0)
            atomicMax(&g_gtkey[n * Tt + tid], m);
    }

    // fused low-quality override: last finishing assignment block applies all
    __syncthreads();
    __threadfence();
    __shared__ bool slast;
    if (tid == 0)
        slast = (atomicAdd(&g_done1, 1u) == (unsigned)(K1B - 1));
    __syncthreads();
    if (slast) {
        for (int idx2 = tid; idx2 < Nn * Tt; idx2 += 256) {
            int nn = idx2 >> 6, k = idx2 & 63;
            if (k < g_nvalid[nn]) {
                unsigned long long key = g_gtkey[nn * Tt + k];
                if ((key >> 32) != 0) {
                    int aa = (int)(~(unsigned)(key & 0xFFFFFFFFull));
                    int t = g_vt[nn * Tt + k];
                    int p = nn * Aa + aa;
                    atomicMax(&g_asg[p], 0x40000000 | t);
                    int old = atomicExch(&g_state[p], 2);
                    if (old != 2) {
                        int pp = atomicAdd(&g_npos, 1);
                        g_poslist[pp] = p;
                        atomicAdd(&g_poscnt[nn], 1);
                    }
                }
            }
        }
    }
}

// ---------------- Launch B: list-driven corrections (branchless) + finalize ----------------
__global__ void __launch_bounds__(256)
kB(const float4* __restrict__ yp4,
   const float4* __restrict__ anchors,
   const float4* __restrict__ bbp4,
   const float* __restrict__ bbox_true,
   float* __restrict__ out) {
    float cls = 0.f, box = 0.f;
    int gtid = blockIdx.x * 256 + threadIdx.x;
    const int stride = QB * 256;

    // ---- ignore subtraction: item = (entry, float4-q); branchless, MLP-friendly ----
    int nI = g_nign;
    int nItems = nI * 20;
    #pragma unroll 2
    for (int it = gtid; it < nItems; it += stride) {
        int e = it / 20;
        int qq = it - e * 20;
        int idx = g_ignlist[e];
        float wgt = (g_state[idx] == 0) ? -0.75f : 0.0f;  // LQ-promoted -> 0
        int n = idx >> 16;
        int a = idx & (Aa - 1);
        float4 vv = yp4[(size_t)n * NFLT4 + (size_t)a * 20 + qq];
        float S = focal_elem(vv.x) + focal_elem(vv.y) +
                  focal_elem(vv.z) + focal_elem(vv.w);
        cls = fmaf(wgt, S, cls);
    }

    // ---- positive corrections: one work item = one pos anchor ----
    int nP = g_npos;
    for (int e = gtid; e < nP; e += stride) {
        int idx = g_poslist[e];
        int n = idx >> 16;
        int a = idx & (Aa - 1);
        const float4* yp = yp4 + (size_t)n * NFLT4 + (size_t)a * 20;
        int v = g_asg[idx];
        int asg = (v & 0x40000000) ? (v & 0xFF) : v;
        int label = (int)g_label[n * Tt + asg];
        float4 vv = yp[label >> 2];
        int j = label & 3;
        float lsel = (j == 0) ? vv.x : ((j == 1) ? vv.y : ((j == 2) ? vv.z : vv.w));
        {
            float mm = fabsf(lsel);
            float em = __expf(-mm);
            float uu = 1.0f + em;
            float r  = rcp_approx(uu);
            float lgv = __logf(uu);
            float p  = (lsel >= 0.f) ? r : em * r;
            float qd = 1.0f - p;
            float ce  = lgv + fmaxf(lsel, 0.f);
            float cep = lgv + fmaxf(-lsel, 0.f);
            cls += 0.25f * qd * qd * cep - 0.75f * p * p * ce;
        }
        float4 an = anchors[a];
        float4 bp = bbp4[idx];
        const float* bt = bbox_true + ((size_t)n * Tt + asg) * 4;
        float bx1 = bt[0], by1 = bt[1], bx2 = bt[2], by2 = bt[3];
        float wa = fmaxf(an.z - an.x, F_EPS);
        float ha = fmaxf(an.w - an.y, F_EPS);
        float cxa = an.x + 0.5f * wa;
        float cya = an.y + 0.5f * ha;
        float wt = fmaxf(bx2 - bx1, F_EPS);
        float ht = fmaxf(by2 - by1, F_EPS);
        float cxt = bx1 + 0.5f * (bx2 - bx1);
        float cyt = by1 + 0.5f * (by2 - by1);
        float tg0 = (cxt - cxa) / wa;
        float tg1 = (cyt - cya) / ha;
        float tg2 = logf(wt / wa);
        float tg3 = logf(ht / ha);
        float d0 = fabsf(tg0 - bp.x), d1 = fabsf(tg1 - bp.y);
        float d2 = fabsf(tg2 - bp.z), d3 = fabsf(tg3 - bp.w);
        box += (d0 < SL1_BETA) ? (0.5f * d0 * d0 / SL1_BETA) : (d0 - 0.5f * SL1_BETA);
        box += (d1 < SL1_BETA) ? (0.5f * d1 * d1 / SL1_BETA) : (d1 - 0.5f * SL1_BETA);
        box += (d2 < SL1_BETA) ? (0.5f * d2 * d2 / SL1_BETA) : (d2 - 0.5f * SL1_BETA);
        box += (d3 < SL1_BETA) ? (0.5f * d3 * d3 / SL1_BETA) : (d3 - 0.5f * SL1_BETA);
    }

    // block reduce
    unsigned full = 0xFFFFFFFFu;
    #pragma unroll
    for (int o = 16; o > 0; o >>= 1) {
        cls += __shfl_down_sync(full, cls, o);
        box += __shfl_down_sync(full, box, o);
    }
    __shared__ float wc[8], wb[8];
    int w = threadIdx.x >> 5, lane = threadIdx.x & 31;
    if (lane == 0) { wc[w] = cls; wb[w] = box; }
    __syncthreads();
    if (threadIdx.x == 0) {
        float c = 0.f, b = 0.f;
        #pragma unroll
        for (int i = 0; i < 8; i++) { c += wc[i]; b += wb[i]; }
        g_qcls[blockIdx.x] = c;
        g_qbox[blockIdx.x] = b;
    }

    // last finishing block: final reduce + output + resets
    __syncthreads();
    __threadfence();
    __shared__ bool slast;
    if (threadIdx.x == 0)
        slast = (atomicAdd(&g_doneB, 1u) == (unsigned)(QB - 1));
    __syncthreads();
    if (!slast) return;

    __shared__ double sc[256], sb2[256];
    int tid = threadIdx.x;
    double c = 0.0, b = 0.0;
    for (int i = tid; i < SBX; i += 256) c += (double)g_pcls[i];
    for (int i = tid; i < QB; i += 256) { c += (double)g_qcls[i]; b += (double)g_qbox[i]; }
    sc[tid] = c; sb2[tid] = b;
    __syncthreads();
    for (int s = 128; s > 0; s >>= 1) {
        if (tid < s) { sc[tid] += sc[tid + s]; sb2[tid] += sb2[tid + s]; }
        __syncthreads();
    }
    if (tid == 0) {
        double avg = 0.0;
        for (int nn = 0; nn < Nn; nn++) {
            double p = (double)g_poscnt[nn];
            avg += (p > 1.0) ? p : 1.0;
        }
        float clsO = (float)(sc[0] / avg);
        float boxO = (float)(sb2[0] / avg);
        if (isnan(clsO) || isinf(clsO)) clsO = 0.f;
        if (isnan(boxO) || isinf(boxO)) boxO = 0.f;
        out[0] = clsO;
        out[1] = boxO;
    }
    // resets for next graph replay
    __syncthreads();
    if (tid == 0) { g_done1 = 0; g_doneB = 0; g_npos = 0; g_nign = 0; }
    if (tid < Nn) g_poscnt[tid] = 0;
    for (int i = tid; i < Nn * Tt; i += 256) g_gtkey[i] = 0ull;
}

// ---------------- launch ----------------
extern "C" void kernel_launch(void* const* d_in, const int* in_sizes, int n_in,
                              void* d_out, int out_size) {
    const float*  y_true    = (const float*)d_in[0];
    const float*  bbox_true = (const float*)d_in[1];
    const float*  y_pred    = (const float*)d_in[2];
    const float4* bbox_pred = (const float4*)d_in[3];
    const float4* anchors   = (const float4*)d_in[4];
    float* out = (float*)d_out;

    kA<<<TOTB, 256>>>(anchors, (const float4*)bbox_true, y_true,
                      (const float4*)y_pred);
    kB<<<QB, 256>>>((const float4*)y_pred, anchors, bbox_pred, bbox_true, out);
}